// round 1
// baseline (speedup 1.0000x reference)
#include <cuda_runtime.h>
#include <math.h>

#define N_TOK 1024
#define C_IN  512
#define CQ    64
#define BATCH 32
#define OC_TOTAL 640   // 64 (q) + 64 (k) + 512 (v)

// ---------------- scratch (device globals; no allocation allowed) ----------
__device__ float g_WnT[C_IN * OC_TOTAL];                       // [c][ocat] spectral-normalized, transposed
__device__ float g_q[(size_t)BATCH * CQ * N_TOK];              // [b][o][n]
__device__ float g_k[(size_t)BATCH * CQ * N_TOK];              // [b][o][n]
__device__ float g_v[(size_t)BATCH * C_IN * N_TOK];            // [b][c][n]
__device__ float g_S[(size_t)BATCH * N_TOK * N_TOK];           // [b][m][n] = qk[b][n][m]

// ---------------- spectral norm ------------------------------------------
// sigma = || W @ normalize(W^T u) ||;  write W/sigma transposed into g_WnT
__global__ void sn_kernel(const float* __restrict__ Wq, const float* __restrict__ uq,
                          const float* __restrict__ Wk, const float* __restrict__ uk,
                          const float* __restrict__ Wv, const float* __restrict__ uv) {
    const float* W; const float* u; int out; int dst;
    if (blockIdx.x == 0)      { W = Wq; u = uq; out = CQ;   dst = 0;      }
    else if (blockIdx.x == 1) { W = Wk; u = uk; out = CQ;   dst = CQ;     }
    else                      { W = Wv; u = uv; out = C_IN; dst = 2 * CQ; }

    __shared__ float su[C_IN];
    __shared__ float sv[C_IN];
    __shared__ float red[512];
    int tid = threadIdx.x;

    if (tid < out) su[tid] = u[tid];
    __syncthreads();

    // t[j] = sum_i W[i][j] * u[i]   (j = tid, in == 512 == blockDim)
    float t = 0.f;
    for (int i = 0; i < out; i++) t += W[i * C_IN + tid] * su[i];

    red[tid] = t * t;
    __syncthreads();
    for (int s = 256; s > 0; s >>= 1) {
        if (tid < s) red[tid] += red[tid + s];
        __syncthreads();
    }
    float nv = sqrtf(red[0]);
    sv[tid] = t / nv;
    __syncthreads();

    // sigma^2 = sum_i ( sum_j W[i][j] v[j] )^2
    float p = 0.f;
    for (int i = tid; i < out; i += blockDim.x) {
        float r = 0.f;
        for (int j = 0; j < C_IN; j++) r += W[i * C_IN + j] * sv[j];
        p += r * r;
    }
    red[tid] = p;
    __syncthreads();
    for (int s = 256; s > 0; s >>= 1) {
        if (tid < s) red[tid] += red[tid + s];
        __syncthreads();
    }
    float inv_sigma = rsqrtf(red[0]);

    for (int e = tid; e < out * C_IN; e += blockDim.x) {
        int i = e >> 9;        // / 512
        int j = e & 511;       // % 512
        g_WnT[j * OC_TOTAL + dst + i] = W[e] * inv_sigma;
    }
}

// ---------------- fused projection GEMM -----------------------------------
// out[ocat, n] = sum_c WnT[c][ocat] * f[b][c][n]  (+bias), routed to q/k/v
__global__ void __launch_bounds__(256) proj_kernel(const float* __restrict__ x,
                                                   const float* __restrict__ bq,
                                                   const float* __restrict__ bk,
                                                   const float* __restrict__ bv) {
    __shared__ float As[16][68];   // [kk][ocat_local]
    __shared__ float Bs[16][68];   // [kk][n_local]
    int b    = blockIdx.z;
    int row0 = blockIdx.y * 64;    // ocat
    int col0 = blockIdx.x * 64;    // n
    int tid  = threadIdx.x;
    int tx = tid & 15, ty = tid >> 4;
    float acc[4][4] = {};
    const float* fb = x + (size_t)b * C_IN * N_TOK;

    for (int k0 = 0; k0 < C_IN; k0 += 16) {
#pragma unroll
        for (int l = 0; l < 4; l++) {
            int e = tid + l * 256;
            int r = e >> 6, c = e & 63;
            As[r][c] = g_WnT[(k0 + r) * OC_TOTAL + row0 + c];
            Bs[r][c] = fb[(size_t)(k0 + r) * N_TOK + col0 + c];
        }
        __syncthreads();
#pragma unroll
        for (int kk = 0; kk < 16; kk++) {
            float4 a4 = *(const float4*)&As[kk][ty * 4];
            float4 b4 = *(const float4*)&Bs[kk][tx * 4];
            float a_[4] = {a4.x, a4.y, a4.z, a4.w};
            float b_[4] = {b4.x, b4.y, b4.z, b4.w};
#pragma unroll
            for (int i = 0; i < 4; i++)
#pragma unroll
                for (int j = 0; j < 4; j++) acc[i][j] += a_[i] * b_[j];
        }
        __syncthreads();
    }

#pragma unroll
    for (int i = 0; i < 4; i++) {
        int o = row0 + ty * 4 + i;
        float bias; float* dst;
        if (o < CQ)           { bias = bq[o];          dst = g_q + ((size_t)b * CQ   + o)          * N_TOK; }
        else if (o < 2 * CQ)  { bias = bk[o - CQ];     dst = g_k + ((size_t)b * CQ   + (o - CQ))   * N_TOK; }
        else                  { bias = bv[o - 2 * CQ]; dst = g_v + ((size_t)b * C_IN + (o - 2*CQ)) * N_TOK; }
        float4 r;
        r.x = acc[i][0] + bias;
        r.y = acc[i][1] + bias;
        r.z = acc[i][2] + bias;
        r.w = acc[i][3] + bias;
        *(float4*)&dst[col0 + tx * 4] = r;
    }
}

// ---------------- QK^T ----------------------------------------------------
// S[b][m][n] = sum_o k[b][o][m] * q[b][o][n]
__global__ void __launch_bounds__(256) qk_kernel() {
    __shared__ float Ks[16][68];   // [o_local][m_local]
    __shared__ float Qs[16][68];   // [o_local][n_local]
    int b  = blockIdx.z;
    int m0 = blockIdx.y * 64;
    int n0 = blockIdx.x * 64;
    int tid = threadIdx.x;
    int tx = tid & 15, ty = tid >> 4;
    float acc[4][4] = {};
    const float* kb = g_k + (size_t)b * CQ * N_TOK;
    const float* qb = g_q + (size_t)b * CQ * N_TOK;

    for (int o0 = 0; o0 < CQ; o0 += 16) {
#pragma unroll
        for (int l = 0; l < 4; l++) {
            int e = tid + l * 256;
            int r = e >> 6, c = e & 63;
            Ks[r][c] = kb[(o0 + r) * N_TOK + m0 + c];
            Qs[r][c] = qb[(o0 + r) * N_TOK + n0 + c];
        }
        __syncthreads();
#pragma unroll
        for (int kk = 0; kk < 16; kk++) {
            float4 a4 = *(const float4*)&Ks[kk][ty * 4];
            float4 b4 = *(const float4*)&Qs[kk][tx * 4];
            float a_[4] = {a4.x, a4.y, a4.z, a4.w};
            float b_[4] = {b4.x, b4.y, b4.z, b4.w};
#pragma unroll
            for (int i = 0; i < 4; i++)
#pragma unroll
                for (int j = 0; j < 4; j++) acc[i][j] += a_[i] * b_[j];
        }
        __syncthreads();
    }

    float* Sb = g_S + (size_t)b * N_TOK * N_TOK;
#pragma unroll
    for (int i = 0; i < 4; i++) {
        float4 r;
        r.x = acc[i][0]; r.y = acc[i][1]; r.z = acc[i][2]; r.w = acc[i][3];
        *(float4*)&Sb[(size_t)(m0 + ty * 4 + i) * N_TOK + n0 + tx * 4] = r;
    }
}

// ---------------- row softmax over n --------------------------------------
__global__ void __launch_bounds__(256) softmax_kernel() {
    int b = blockIdx.y, m = blockIdx.x;
    float* row = g_S + ((size_t)b * N_TOK + m) * N_TOK;
    int tid = threadIdx.x;
    __shared__ float sm[8];

    float4 v = ((float4*)row)[tid];
    float mx = fmaxf(fmaxf(v.x, v.y), fmaxf(v.z, v.w));
#pragma unroll
    for (int s = 16; s; s >>= 1) mx = fmaxf(mx, __shfl_xor_sync(0xffffffffu, mx, s));
    if ((tid & 31) == 0) sm[tid >> 5] = mx;
    __syncthreads();
    mx = sm[0];
#pragma unroll
    for (int w = 1; w < 8; w++) mx = fmaxf(mx, sm[w]);
    __syncthreads();

    v.x = __expf(v.x - mx);
    v.y = __expf(v.y - mx);
    v.z = __expf(v.z - mx);
    v.w = __expf(v.w - mx);
    float s4 = v.x + v.y + v.z + v.w;
#pragma unroll
    for (int s = 16; s; s >>= 1) s4 += __shfl_xor_sync(0xffffffffu, s4, s);
    if ((tid & 31) == 0) sm[tid >> 5] = s4;
    __syncthreads();
    float tot = 0.f;
#pragma unroll
    for (int w = 0; w < 8; w++) tot += sm[w];
    float inv = 1.f / tot;
    v.x *= inv; v.y *= inv; v.z *= inv; v.w *= inv;
    ((float4*)row)[tid] = v;
}

// ---------------- AV + epilogue -------------------------------------------
// out[b][c][m] = gamma * sum_n v[b][c][n] * A[b][m][n] + x[b][c][m]
__global__ void __launch_bounds__(256) av_kernel(const float* __restrict__ x,
                                                 const float* __restrict__ gamma_p,
                                                 float* __restrict__ out) {
    __shared__ float Vs[16][68];   // [n_local][c_local]   (transposed on store)
    __shared__ float Ss[16][68];   // [n_local][m_local]   (transposed on store)
    int b  = blockIdx.z;
    int c0 = blockIdx.y * 64;
    int m0 = blockIdx.x * 64;
    int tid = threadIdx.x;
    int tx = tid & 15, ty = tid >> 4;
    float acc[4][4] = {};
    const float* vb = g_v + (size_t)b * C_IN * N_TOK;
    const float* Sb = g_S + (size_t)b * N_TOK * N_TOK;

    for (int n0 = 0; n0 < N_TOK; n0 += 16) {
#pragma unroll
        for (int l = 0; l < 4; l++) {
            int e = tid + l * 256;
            int rr = e >> 4, cc = e & 15;
            Vs[cc][rr] = vb[(size_t)(c0 + rr) * N_TOK + n0 + cc];
            Ss[cc][rr] = Sb[(size_t)(m0 + rr) * N_TOK + n0 + cc];
        }
        __syncthreads();
#pragma unroll
        for (int kk = 0; kk < 16; kk++) {
            float4 a4 = *(const float4*)&Vs[kk][ty * 4];
            float4 b4 = *(const float4*)&Ss[kk][tx * 4];
            float a_[4] = {a4.x, a4.y, a4.z, a4.w};
            float b_[4] = {b4.x, b4.y, b4.z, b4.w};
#pragma unroll
            for (int i = 0; i < 4; i++)
#pragma unroll
                for (int j = 0; j < 4; j++) acc[i][j] += a_[i] * b_[j];
        }
        __syncthreads();
    }

    float g = *gamma_p;
    size_t base = (size_t)b * C_IN * N_TOK;
#pragma unroll
    for (int i = 0; i < 4; i++) {
        int c = c0 + ty * 4 + i;
        size_t off = base + (size_t)c * N_TOK + m0 + tx * 4;
        float4 xv = *(const float4*)&x[off];
        float4 r;
        r.x = g * acc[i][0] + xv.x;
        r.y = g * acc[i][1] + xv.y;
        r.z = g * acc[i][2] + xv.z;
        r.w = g * acc[i][3] + xv.w;
        *(float4*)&out[off] = r;
    }
}

// ---------------- launch ---------------------------------------------------
extern "C" void kernel_launch(void* const* d_in, const int* in_sizes, int n_in,
                              void* d_out, int out_size) {
    const float* x     = (const float*)d_in[0];
    const float* Wq    = (const float*)d_in[1];
    const float* bq    = (const float*)d_in[2];
    const float* uq    = (const float*)d_in[3];
    const float* Wk    = (const float*)d_in[4];
    const float* bk    = (const float*)d_in[5];
    const float* uk    = (const float*)d_in[6];
    const float* Wv    = (const float*)d_in[7];
    const float* bv    = (const float*)d_in[8];
    const float* uv    = (const float*)d_in[9];
    const float* gamma = (const float*)d_in[10];
    float* out = (float*)d_out;

    sn_kernel<<<3, 512>>>(Wq, uq, Wk, uk, Wv, uv);
    proj_kernel<<<dim3(16, 10, BATCH), 256>>>(x, bq, bk, bv);
    qk_kernel<<<dim3(16, 16, BATCH), 256>>>();
    softmax_kernel<<<dim3(N_TOK, BATCH), 256>>>();
    av_kernel<<<dim3(16, 8, BATCH), 256>>>(x, gamma, out);
}

// round 2
// speedup vs baseline: 1.1087x; 1.1087x over previous
#include <cuda_runtime.h>
#include <math.h>

#define N_TOK 1024
#define C_IN  512
#define CQ    64
#define BATCH 32
#define OC_TOTAL 640   // 64 (q) + 64 (k) + 512 (v)

// ---------------- scratch (device globals; no allocation allowed) ----------
__device__ float g_WnT[C_IN * OC_TOTAL];                       // [c][ocat] spectral-normalized, transposed
__device__ float g_q[(size_t)BATCH * CQ * N_TOK];              // [b][o][n]
__device__ float g_k[(size_t)BATCH * CQ * N_TOK];              // [b][o][n]
__device__ float g_v[(size_t)BATCH * C_IN * N_TOK];            // [b][c][n]
__device__ float g_S[(size_t)BATCH * N_TOK * N_TOK];           // [b][m][n]

// ---------------- spectral norm ------------------------------------------
__global__ void sn_kernel(const float* __restrict__ Wq, const float* __restrict__ uq,
                          const float* __restrict__ Wk, const float* __restrict__ uk,
                          const float* __restrict__ Wv, const float* __restrict__ uv) {
    const float* W; const float* u; int out; int dst;
    if (blockIdx.x == 0)      { W = Wq; u = uq; out = CQ;   dst = 0;      }
    else if (blockIdx.x == 1) { W = Wk; u = uk; out = CQ;   dst = CQ;     }
    else                      { W = Wv; u = uv; out = C_IN; dst = 2 * CQ; }

    __shared__ float su[C_IN];
    __shared__ float sv[C_IN];
    __shared__ float red[512];
    int tid = threadIdx.x;

    if (tid < out) su[tid] = u[tid];
    __syncthreads();

    float t = 0.f;
    for (int i = 0; i < out; i++) t += W[i * C_IN + tid] * su[i];

    red[tid] = t * t;
    __syncthreads();
    for (int s = 256; s > 0; s >>= 1) {
        if (tid < s) red[tid] += red[tid + s];
        __syncthreads();
    }
    float nv = sqrtf(red[0]);
    sv[tid] = t / nv;
    __syncthreads();

    float p = 0.f;
    for (int i = tid; i < out; i += blockDim.x) {
        float r = 0.f;
        for (int j = 0; j < C_IN; j++) r += W[i * C_IN + j] * sv[j];
        p += r * r;
    }
    red[tid] = p;
    __syncthreads();
    for (int s = 256; s > 0; s >>= 1) {
        if (tid < s) red[tid] += red[tid + s];
        __syncthreads();
    }
    float inv_sigma = rsqrtf(red[0]);

    for (int e = tid; e < out * C_IN; e += blockDim.x) {
        int i = e >> 9;
        int j = e & 511;
        g_WnT[j * OC_TOTAL + dst + i] = W[e] * inv_sigma;
    }
}

// ---------------- 8x8 microtile FMA core -----------------------------------
template<int LD>
__device__ __forceinline__ void mm_tile(const float (*As)[LD], const float (*Bs)[LD],
                                        float acc[8][8], int ty8, int tx8) {
#pragma unroll
    for (int kk = 0; kk < 8; kk++) {
        float4 a0 = *(const float4*)&As[kk][ty8];
        float4 a1 = *(const float4*)&As[kk][ty8 + 4];
        float4 b0 = *(const float4*)&Bs[kk][tx8];
        float4 b1 = *(const float4*)&Bs[kk][tx8 + 4];
        float a_[8] = {a0.x, a0.y, a0.z, a0.w, a1.x, a1.y, a1.z, a1.w};
        float b_[8] = {b0.x, b0.y, b0.z, b0.w, b1.x, b1.y, b1.z, b1.w};
#pragma unroll
        for (int i = 0; i < 8; i++)
#pragma unroll
            for (int j = 0; j < 8; j++) acc[i][j] += a_[i] * b_[j];
    }
}

// ---------------- fused projection GEMM: 128x128 tile ----------------------
// out[ocat, n] = sum_c WnT[c][ocat] * f[b][c][n]  (+bias), routed to q/k/v
__global__ void __launch_bounds__(256) proj_kernel(const float* __restrict__ x,
                                                   const float* __restrict__ bq,
                                                   const float* __restrict__ bk,
                                                   const float* __restrict__ bv) {
    __shared__ float As[2][8][128];
    __shared__ float Bs[2][8][128];
    int b    = blockIdx.z;
    int row0 = blockIdx.y * 128;   // ocat
    int col0 = blockIdx.x * 128;   // n
    int tid  = threadIdx.x;
    int tx = tid & 15, ty = tid >> 4;
    int tx8 = tx * 8, ty8 = ty * 8;
    int lr = tid >> 5, lc = (tid & 31) * 4;
    const float* fb = x + (size_t)b * C_IN * N_TOK;
    float acc[8][8] = {};

    float4 ra = *(const float4*)&g_WnT[lr * OC_TOTAL + row0 + lc];
    float4 rb = *(const float4*)&fb[(size_t)lr * N_TOK + col0 + lc];
    const int KT = C_IN / 8;
    for (int kt = 0; kt < KT; kt++) {
        int p = kt & 1;
        *(float4*)&As[p][lr][lc] = ra;
        *(float4*)&Bs[p][lr][lc] = rb;
        __syncthreads();
        if (kt + 1 < KT) {
            int k0 = (kt + 1) * 8;
            ra = *(const float4*)&g_WnT[(k0 + lr) * OC_TOTAL + row0 + lc];
            rb = *(const float4*)&fb[(size_t)(k0 + lr) * N_TOK + col0 + lc];
        }
        mm_tile<128>(As[p], Bs[p], acc, ty8, tx8);
        __syncthreads();
    }

#pragma unroll
    for (int i = 0; i < 8; i++) {
        int o = row0 + ty8 + i;
        float bias; float* dst;
        if (o < CQ)           { bias = bq[o];          dst = g_q + ((size_t)b * CQ   + o)            * N_TOK; }
        else if (o < 2 * CQ)  { bias = bk[o - CQ];     dst = g_k + ((size_t)b * CQ   + (o - CQ))     * N_TOK; }
        else                  { bias = bv[o - 2 * CQ]; dst = g_v + ((size_t)b * C_IN + (o - 2 * CQ)) * N_TOK; }
        float4 r0, r1;
        r0.x = acc[i][0] + bias; r0.y = acc[i][1] + bias;
        r0.z = acc[i][2] + bias; r0.w = acc[i][3] + bias;
        r1.x = acc[i][4] + bias; r1.y = acc[i][5] + bias;
        r1.z = acc[i][6] + bias; r1.w = acc[i][7] + bias;
        *(float4*)&dst[col0 + tx8]     = r0;
        *(float4*)&dst[col0 + tx8 + 4] = r1;
    }
}

// ---------------- QK^T: 128x128 tile ---------------------------------------
// S[b][m][n] = sum_o k[b][o][m] * q[b][o][n]
__global__ void __launch_bounds__(256) qk_kernel() {
    __shared__ float As[2][8][128];
    __shared__ float Bs[2][8][128];
    int b  = blockIdx.z;
    int m0 = blockIdx.y * 128;
    int n0 = blockIdx.x * 128;
    int tid = threadIdx.x;
    int tx = tid & 15, ty = tid >> 4;
    int tx8 = tx * 8, ty8 = ty * 8;
    int lr = tid >> 5, lc = (tid & 31) * 4;
    const float* kb = g_k + (size_t)b * CQ * N_TOK;
    const float* qb = g_q + (size_t)b * CQ * N_TOK;
    float acc[8][8] = {};

    float4 ra = *(const float4*)&kb[(size_t)lr * N_TOK + m0 + lc];
    float4 rb = *(const float4*)&qb[(size_t)lr * N_TOK + n0 + lc];
    const int KT = CQ / 8;
    for (int kt = 0; kt < KT; kt++) {
        int p = kt & 1;
        *(float4*)&As[p][lr][lc] = ra;
        *(float4*)&Bs[p][lr][lc] = rb;
        __syncthreads();
        if (kt + 1 < KT) {
            int k0 = (kt + 1) * 8;
            ra = *(const float4*)&kb[(size_t)(k0 + lr) * N_TOK + m0 + lc];
            rb = *(const float4*)&qb[(size_t)(k0 + lr) * N_TOK + n0 + lc];
        }
        mm_tile<128>(As[p], Bs[p], acc, ty8, tx8);
        __syncthreads();
    }

    float* Sb = g_S + (size_t)b * N_TOK * N_TOK;
#pragma unroll
    for (int i = 0; i < 8; i++) {
        float4 r0, r1;
        r0.x = acc[i][0]; r0.y = acc[i][1]; r0.z = acc[i][2]; r0.w = acc[i][3];
        r1.x = acc[i][4]; r1.y = acc[i][5]; r1.z = acc[i][6]; r1.w = acc[i][7];
        size_t off = (size_t)(m0 + ty8 + i) * N_TOK + n0 + tx8;
        *(float4*)&Sb[off]     = r0;
        *(float4*)&Sb[off + 4] = r1;
    }
}

// ---------------- row softmax over n --------------------------------------
__global__ void __launch_bounds__(256) softmax_kernel() {
    int b = blockIdx.y, m = blockIdx.x;
    float* row = g_S + ((size_t)b * N_TOK + m) * N_TOK;
    int tid = threadIdx.x;
    __shared__ float sm[8];

    float4 v = ((float4*)row)[tid];
    float mx = fmaxf(fmaxf(v.x, v.y), fmaxf(v.z, v.w));
#pragma unroll
    for (int s = 16; s; s >>= 1) mx = fmaxf(mx, __shfl_xor_sync(0xffffffffu, mx, s));
    if ((tid & 31) == 0) sm[tid >> 5] = mx;
    __syncthreads();
    mx = sm[0];
#pragma unroll
    for (int w = 1; w < 8; w++) mx = fmaxf(mx, sm[w]);
    __syncthreads();

    v.x = __expf(v.x - mx);
    v.y = __expf(v.y - mx);
    v.z = __expf(v.z - mx);
    v.w = __expf(v.w - mx);
    float s4 = v.x + v.y + v.z + v.w;
#pragma unroll
    for (int s = 16; s; s >>= 1) s4 += __shfl_xor_sync(0xffffffffu, s4, s);
    if ((tid & 31) == 0) sm[tid >> 5] = s4;
    __syncthreads();
    float tot = 0.f;
#pragma unroll
    for (int w = 0; w < 8; w++) tot += sm[w];
    float inv = 1.f / tot;
    v.x *= inv; v.y *= inv; v.z *= inv; v.w *= inv;
    ((float4*)row)[tid] = v;
}

// ---------------- AV + epilogue: 128x128 tile -------------------------------
// out[b][c][m] = gamma * sum_n v[b][c][n] * A[b][m][n] + x[b][c][m]
// Both operands are M-major (contiguous along K=n): transposed smem stores,
// padding 132 makes the 32-thread scatter pattern conflict-free.
__global__ void __launch_bounds__(256) av_kernel(const float* __restrict__ x,
                                                 const float* __restrict__ gamma_p,
                                                 float* __restrict__ out) {
    __shared__ float As[2][8][132];   // [n_local][c_local]
    __shared__ float Bs[2][8][132];   // [n_local][m_local]
    int b  = blockIdx.z;
    int c0 = blockIdx.y * 128;
    int m0 = blockIdx.x * 128;
    int tid = threadIdx.x;
    int tx = tid & 15, ty = tid >> 4;
    int tx8 = tx * 8, ty8 = ty * 8;
    int lm = tid >> 1, kc = (tid & 1) * 4;
    const float* vb = g_v + (size_t)b * C_IN * N_TOK;
    const float* Sb = g_S + (size_t)b * N_TOK * N_TOK;
    float acc[8][8] = {};

    float4 ra = *(const float4*)&vb[(size_t)(c0 + lm) * N_TOK + kc];
    float4 rb = *(const float4*)&Sb[(size_t)(m0 + lm) * N_TOK + kc];
    const int KT = N_TOK / 8;
    for (int kt = 0; kt < KT; kt++) {
        int p = kt & 1;
        As[p][kc + 0][lm] = ra.x; As[p][kc + 1][lm] = ra.y;
        As[p][kc + 2][lm] = ra.z; As[p][kc + 3][lm] = ra.w;
        Bs[p][kc + 0][lm] = rb.x; Bs[p][kc + 1][lm] = rb.y;
        Bs[p][kc + 2][lm] = rb.z; Bs[p][kc + 3][lm] = rb.w;
        __syncthreads();
        if (kt + 1 < KT) {
            int n0 = (kt + 1) * 8;
            ra = *(const float4*)&vb[(size_t)(c0 + lm) * N_TOK + n0 + kc];
            rb = *(const float4*)&Sb[(size_t)(m0 + lm) * N_TOK + n0 + kc];
        }
        mm_tile<132>(As[p], Bs[p], acc, ty8, tx8);
        __syncthreads();
    }

    float g = *gamma_p;
    size_t base = (size_t)b * C_IN * N_TOK;
#pragma unroll
    for (int i = 0; i < 8; i++) {
        int c = c0 + ty8 + i;
        size_t off = base + (size_t)c * N_TOK + m0 + tx8;
        float4 x0 = *(const float4*)&x[off];
        float4 x1 = *(const float4*)&x[off + 4];
        float4 r0, r1;
        r0.x = g * acc[i][0] + x0.x; r0.y = g * acc[i][1] + x0.y;
        r0.z = g * acc[i][2] + x0.z; r0.w = g * acc[i][3] + x0.w;
        r1.x = g * acc[i][4] + x1.x; r1.y = g * acc[i][5] + x1.y;
        r1.z = g * acc[i][6] + x1.z; r1.w = g * acc[i][7] + x1.w;
        *(float4*)&out[off]     = r0;
        *(float4*)&out[off + 4] = r1;
    }
}

// ---------------- launch ---------------------------------------------------
extern "C" void kernel_launch(void* const* d_in, const int* in_sizes, int n_in,
                              void* d_out, int out_size) {
    const float* x     = (const float*)d_in[0];
    const float* Wq    = (const float*)d_in[1];
    const float* bq    = (const float*)d_in[2];
    const float* uq    = (const float*)d_in[3];
    const float* Wk    = (const float*)d_in[4];
    const float* bk    = (const float*)d_in[5];
    const float* uk    = (const float*)d_in[6];
    const float* Wv    = (const float*)d_in[7];
    const float* bv    = (const float*)d_in[8];
    const float* uv    = (const float*)d_in[9];
    const float* gamma = (const float*)d_in[10];
    float* out = (float*)d_out;

    sn_kernel<<<3, 512>>>(Wq, uq, Wk, uk, Wv, uv);
    proj_kernel<<<dim3(8, 5, BATCH), 256>>>(x, bq, bk, bv);
    qk_kernel<<<dim3(8, 8, BATCH), 256>>>();
    softmax_kernel<<<dim3(N_TOK, BATCH), 256>>>();
    av_kernel<<<dim3(8, 4, BATCH), 256>>>(x, gamma, out);
}

// round 4
// speedup vs baseline: 1.8886x; 1.7034x over previous
#include <cuda_runtime.h>
#include <cuda_bf16.h>
#include <math.h>
#include <stdint.h>

#define N_TOK 1024
#define C_IN  512
#define CQ    64
#define BATCH 32

// ---------------- scratch (device globals; no allocation allowed) ----------
__device__ __align__(128) float g_Wn [640 * C_IN];                   // rows: q 0-63, k 64-127, v 128-639 (K-major)
__device__ __align__(128) float g_bias[640];
__device__ __align__(128) float g_xT [(size_t)BATCH * N_TOK * C_IN]; // [b][n][c]
__device__ __align__(128) float g_qT [(size_t)BATCH * N_TOK * CQ];   // [b][n][o]
__device__ __align__(128) float g_kT [(size_t)BATCH * N_TOK * CQ];   // [b][m][o]
__device__ __align__(128) float g_v  [(size_t)BATCH * C_IN * N_TOK]; // [b][c][n]
__device__ __align__(128) float g_S  [(size_t)BATCH * N_TOK * N_TOK];// [b][m][n]

// ---------------- bf16 split helpers ----------------------------------------
__device__ __forceinline__ void split2(float a, float b, uint32_t& h, uint32_t& l) {
    __nv_bfloat16 ah = __float2bfloat16(a);
    __nv_bfloat16 bh = __float2bfloat16(b);
    __nv_bfloat16 al = __float2bfloat16(a - __bfloat162float(ah));
    __nv_bfloat16 bl = __float2bfloat16(b - __bfloat162float(bh));
    h = (uint32_t)__bfloat16_as_ushort(ah) | ((uint32_t)__bfloat16_as_ushort(bh) << 16);
    l = (uint32_t)__bfloat16_as_ushort(al) | ((uint32_t)__bfloat16_as_ushort(bl) << 16);
}

__device__ __forceinline__ void mma_bf16(float c[4], const uint32_t a[4], const uint32_t b[2]) {
    asm volatile(
        "mma.sync.aligned.m16n8k16.row.col.f32.bf16.bf16.f32 "
        "{%0,%1,%2,%3}, {%4,%5,%6,%7}, {%8,%9}, {%0,%1,%2,%3};"
        : "+f"(c[0]), "+f"(c[1]), "+f"(c[2]), "+f"(c[3])
        : "r"(a[0]), "r"(a[1]), "r"(a[2]), "r"(a[3]), "r"(b[0]), "r"(b[1]));
}

// fetch one 128x32 fp32 chunk: each of 256 threads grabs 16 floats (row tid>>1,
// cols kbase + (tid&1)*16 .. +15)
__device__ __forceinline__ void fetch4(const float* __restrict__ src, int stride, int kbase,
                                       int tid, float4 f[4]) {
    int r = tid >> 1, c = kbase + (tid & 1) * 16;
    const float* p = src + (size_t)r * stride + c;
    f[0] = *(const float4*)(p + 0);
    f[1] = *(const float4*)(p + 4);
    f[2] = *(const float4*)(p + 8);
    f[3] = *(const float4*)(p + 12);
}

// commit to smem (80B-padded rows: 20 u32 per row of 32 bf16 data)
__device__ __forceinline__ void commit4(const float4 f[4], uint32_t* hi, uint32_t* lo, int tid) {
    int r = tid >> 1, hf = tid & 1;
    uint32_t h[8], l[8];
    split2(f[0].x, f[0].y, h[0], l[0]); split2(f[0].z, f[0].w, h[1], l[1]);
    split2(f[1].x, f[1].y, h[2], l[2]); split2(f[1].z, f[1].w, h[3], l[3]);
    split2(f[2].x, f[2].y, h[4], l[4]); split2(f[2].z, f[2].w, h[5], l[5]);
    split2(f[3].x, f[3].y, h[6], l[6]); split2(f[3].z, f[3].w, h[7], l[7]);
    int idx = r * 20 + hf * 8;
    *(uint4*)(hi + idx)     = make_uint4(h[0], h[1], h[2], h[3]);
    *(uint4*)(hi + idx + 4) = make_uint4(h[4], h[5], h[6], h[7]);
    *(uint4*)(lo + idx)     = make_uint4(l[0], l[1], l[2], l[3]);
    *(uint4*)(lo + idx + 4) = make_uint4(l[4], l[5], l[6], l[7]);
}

// ---------------- shared GEMM core ------------------------------------------
// D[128][128] += A[128 rows, K]·B[128 rows, K]^T, both K-major fp32 in gmem,
// bf16-split 3-product accumulation. 256 threads, 8 warps (2m x 4n), warp tile 64x32.
template<int KT>
__device__ __forceinline__ void gemm_core(const float* __restrict__ A, int sA,
                                          const float* __restrict__ B, int sB,
                                          float acc[4][4][4], uint32_t* sm) {
    const int tid = threadIdx.x;
    const int lane = tid & 31, wid = tid >> 5;
    const int wm = wid & 1, wn = wid >> 1;
    const int g = lane >> 2, tg = lane & 3;
    uint32_t* AHI = sm;
    uint32_t* ALO = sm + 2560;
    uint32_t* BHI = sm + 5120;
    uint32_t* BLO = sm + 7680;

    float4 fa[4], fb[4];
    fetch4(A, sA, 0, tid, fa);
    fetch4(B, sB, 0, tid, fb);
    for (int kt = 0; kt < KT; kt++) {
        commit4(fa, AHI, ALO, tid);
        commit4(fb, BHI, BLO, tid);
        __syncthreads();
        if (kt + 1 < KT) {
            fetch4(A, sA, (kt + 1) * 32, tid, fa);
            fetch4(B, sB, (kt + 1) * 32, tid, fb);
        }
#pragma unroll
        for (int ks = 0; ks < 2; ks++) {
            uint32_t ah[4][4], al[4][4], bh[4][2], bl[4][2];
#pragma unroll
            for (int mt = 0; mt < 4; mt++) {
                int row = wm * 64 + mt * 16 + g;
#pragma unroll
                for (int i = 0; i < 4; i++) {
                    int idx = (row + (i & 1) * 8) * 20 + tg + (i >> 1) * 4 + ks * 8;
                    ah[mt][i] = AHI[idx];
                    al[mt][i] = ALO[idx];
                }
            }
#pragma unroll
            for (int nt = 0; nt < 4; nt++) {
                int row = wn * 32 + nt * 8 + g;
#pragma unroll
                for (int j = 0; j < 2; j++) {
                    int idx = row * 20 + tg + j * 4 + ks * 8;
                    bh[nt][j] = BHI[idx];
                    bl[nt][j] = BLO[idx];
                }
            }
#pragma unroll
            for (int mt = 0; mt < 4; mt++)
#pragma unroll
                for (int nt = 0; nt < 4; nt++) {
                    mma_bf16(acc[mt][nt], ah[mt], bh[nt]);
                    mma_bf16(acc[mt][nt], ah[mt], bl[nt]);
                    mma_bf16(acc[mt][nt], al[mt], bh[nt]);
                }
        }
        __syncthreads();
    }
}

// ---------------- spectral norm ---------------------------------------------
__global__ void sn_kernel(const float* __restrict__ Wq, const float* __restrict__ uq, const float* __restrict__ bq,
                          const float* __restrict__ Wk, const float* __restrict__ uk, const float* __restrict__ bk,
                          const float* __restrict__ Wv, const float* __restrict__ uv, const float* __restrict__ bv) {
    const float* W; const float* u; const float* bias; int out; int dst;
    if (blockIdx.x == 0)      { W = Wq; u = uq; bias = bq; out = CQ;   dst = 0;   }
    else if (blockIdx.x == 1) { W = Wk; u = uk; bias = bk; out = CQ;   dst = 64;  }
    else                      { W = Wv; u = uv; bias = bv; out = C_IN; dst = 128; }

    __shared__ float su[C_IN];
    __shared__ float sv[C_IN];
    __shared__ float red[512];
    int tid = threadIdx.x;

    if (tid < out) { su[tid] = u[tid]; g_bias[dst + tid] = bias[tid]; }
    __syncthreads();

    float t = 0.f;
    for (int i = 0; i < out; i++) t += W[i * C_IN + tid] * su[i];
    red[tid] = t * t;
    __syncthreads();
    for (int s = 256; s > 0; s >>= 1) { if (tid < s) red[tid] += red[tid + s]; __syncthreads(); }
    float nv = sqrtf(red[0]);
    sv[tid] = t / nv;
    __syncthreads();

    float p = 0.f;
    for (int i = tid; i < out; i += blockDim.x) {
        float r = 0.f;
        for (int j = 0; j < C_IN; j++) r += W[i * C_IN + j] * sv[j];
        p += r * r;
    }
    red[tid] = p;
    __syncthreads();
    for (int s = 256; s > 0; s >>= 1) { if (tid < s) red[tid] += red[tid + s]; __syncthreads(); }
    float inv_sigma = rsqrtf(red[0]);

    for (int e = tid; e < out * C_IN; e += blockDim.x)
        g_Wn[(size_t)dst * C_IN + e] = W[e] * inv_sigma;
}

// ---------------- x transpose: xT[b][n][c] ----------------------------------
__global__ void transpose_kernel(const float* __restrict__ x) {
    __shared__ float t[32][33];
    int b = blockIdx.z, c0 = blockIdx.y * 32, n0 = blockIdx.x * 32;
    int tx = threadIdx.x, ty = threadIdx.y;
    const float* src = x + (size_t)b * C_IN * N_TOK;
    float* dst = g_xT + (size_t)b * N_TOK * C_IN;
#pragma unroll
    for (int i = ty; i < 32; i += 8) t[i][tx] = src[(size_t)(c0 + i) * N_TOK + n0 + tx];
    __syncthreads();
#pragma unroll
    for (int i = ty; i < 32; i += 8) dst[(size_t)(n0 + i) * C_IN + c0 + tx] = t[tx][i];
}

// ---------------- proj_qk: D[n][o] = xT · Wqk^T -----------------------------
__global__ void __launch_bounds__(256) proj_qk_kernel() {
    extern __shared__ uint32_t sm[];
    int b = blockIdx.z, m0 = blockIdx.x * 128;   // n-dim tile
    float acc[4][4][4] = {};
    gemm_core<16>(g_xT + ((size_t)b * N_TOK + m0) * C_IN, C_IN, g_Wn, C_IN, acc, sm);

    int tid = threadIdx.x, lane = tid & 31, wid = tid >> 5;
    int wm = wid & 1, wn = wid >> 1, g = lane >> 2, tg = lane & 3;
#pragma unroll
    for (int mt = 0; mt < 4; mt++)
#pragma unroll
        for (int nt = 0; nt < 4; nt++) {
            int r = m0 + wm * 64 + mt * 16 + g;
            int o = wn * 32 + nt * 8 + tg * 2;
            float b0 = g_bias[o], b1 = g_bias[o + 1];
            float* dst0 = (o < 64) ? (g_qT + ((size_t)b * N_TOK + r) * CQ + o)
                                   : (g_kT + ((size_t)b * N_TOK + r) * CQ + (o - 64));
            *(float2*)dst0 = make_float2(acc[mt][nt][0] + b0, acc[mt][nt][1] + b1);
            float* dst1 = (o < 64) ? (g_qT + ((size_t)b * N_TOK + r + 8) * CQ + o)
                                   : (g_kT + ((size_t)b * N_TOK + r + 8) * CQ + (o - 64));
            *(float2*)dst1 = make_float2(acc[mt][nt][2] + b0, acc[mt][nt][3] + b1);
        }
}

// ---------------- proj_v: D[c][n] = Wv · xT^T -------------------------------
__global__ void __launch_bounds__(256) proj_v_kernel() {
    extern __shared__ uint32_t sm[];
    int b = blockIdx.z, m0 = blockIdx.x * 128, n0 = blockIdx.y * 128;  // c, n
    float acc[4][4][4] = {};
    gemm_core<16>(g_Wn + (size_t)(128 + m0) * C_IN, C_IN,
                  g_xT + ((size_t)b * N_TOK + n0) * C_IN, C_IN, acc, sm);

    int tid = threadIdx.x, lane = tid & 31, wid = tid >> 5;
    int wm = wid & 1, wn = wid >> 1, g = lane >> 2, tg = lane & 3;
#pragma unroll
    for (int mt = 0; mt < 4; mt++)
#pragma unroll
        for (int nt = 0; nt < 4; nt++) {
            int c = m0 + wm * 64 + mt * 16 + g;
            int n = n0 + wn * 32 + nt * 8 + tg * 2;
            float b0 = g_bias[128 + c], b1 = g_bias[128 + c + 8];
            float* d0 = g_v + ((size_t)b * C_IN + c) * N_TOK + n;
            float* d1 = g_v + ((size_t)b * C_IN + c + 8) * N_TOK + n;
            *(float2*)d0 = make_float2(acc[mt][nt][0] + b0, acc[mt][nt][1] + b0);
            *(float2*)d1 = make_float2(acc[mt][nt][2] + b1, acc[mt][nt][3] + b1);
        }
}

// ---------------- qk: S[m][n] = kT · qT^T -----------------------------------
__global__ void __launch_bounds__(256) qk_kernel() {
    extern __shared__ uint32_t sm[];
    int b = blockIdx.z, m0 = blockIdx.x * 128, n0 = blockIdx.y * 128;
    float acc[4][4][4] = {};
    gemm_core<2>(g_kT + ((size_t)b * N_TOK + m0) * CQ, CQ,
                 g_qT + ((size_t)b * N_TOK + n0) * CQ, CQ, acc, sm);

    int tid = threadIdx.x, lane = tid & 31, wid = tid >> 5;
    int wm = wid & 1, wn = wid >> 1, g = lane >> 2, tg = lane & 3;
    float* Sb = g_S + (size_t)b * N_TOK * N_TOK;
#pragma unroll
    for (int mt = 0; mt < 4; mt++)
#pragma unroll
        for (int nt = 0; nt < 4; nt++) {
            int m = m0 + wm * 64 + mt * 16 + g;
            int n = n0 + wn * 32 + nt * 8 + tg * 2;
            *(float2*)(Sb + (size_t)m * N_TOK + n)       = make_float2(acc[mt][nt][0], acc[mt][nt][1]);
            *(float2*)(Sb + (size_t)(m + 8) * N_TOK + n) = make_float2(acc[mt][nt][2], acc[mt][nt][3]);
        }
}

// ---------------- row softmax over n ----------------------------------------
__global__ void __launch_bounds__(256) softmax_kernel() {
    int b = blockIdx.y, m = blockIdx.x;
    float* row = g_S + ((size_t)b * N_TOK + m) * N_TOK;
    int tid = threadIdx.x;
    __shared__ float smr[8];

    float4 v = ((float4*)row)[tid];
    float mx = fmaxf(fmaxf(v.x, v.y), fmaxf(v.z, v.w));
#pragma unroll
    for (int s = 16; s; s >>= 1) mx = fmaxf(mx, __shfl_xor_sync(0xffffffffu, mx, s));
    if ((tid & 31) == 0) smr[tid >> 5] = mx;
    __syncthreads();
    mx = smr[0];
#pragma unroll
    for (int w = 1; w < 8; w++) mx = fmaxf(mx, smr[w]);
    __syncthreads();

    v.x = __expf(v.x - mx); v.y = __expf(v.y - mx);
    v.z = __expf(v.z - mx); v.w = __expf(v.w - mx);
    float s4 = v.x + v.y + v.z + v.w;
#pragma unroll
    for (int s = 16; s; s >>= 1) s4 += __shfl_xor_sync(0xffffffffu, s4, s);
    if ((tid & 31) == 0) smr[tid >> 5] = s4;
    __syncthreads();
    float tot = 0.f;
#pragma unroll
    for (int w = 0; w < 8; w++) tot += smr[w];
    float inv = 1.f / tot;
    v.x *= inv; v.y *= inv; v.z *= inv; v.w *= inv;
    ((float4*)row)[tid] = v;
}

// ---------------- av: out[c][m] = gamma*(v · P^T) + x -----------------------
__global__ void __launch_bounds__(256) av_kernel(const float* __restrict__ x,
                                                 const float* __restrict__ gamma_p,
                                                 float* __restrict__ out) {
    extern __shared__ uint32_t sm[];
    int b = blockIdx.z, m0 = blockIdx.x * 128, n0 = blockIdx.y * 128;  // c, m
    float acc[4][4][4] = {};
    gemm_core<32>(g_v + ((size_t)b * C_IN + m0) * N_TOK, N_TOK,
                  g_S + ((size_t)b * N_TOK + n0) * N_TOK, N_TOK, acc, sm);

    int tid = threadIdx.x, lane = tid & 31, wid = tid >> 5;
    int wm = wid & 1, wn = wid >> 1, g = lane >> 2, tg = lane & 3;
    float gam = *gamma_p;
    size_t base = (size_t)b * C_IN * N_TOK;
#pragma unroll
    for (int mt = 0; mt < 4; mt++)
#pragma unroll
        for (int nt = 0; nt < 4; nt++) {
            int c = m0 + wm * 64 + mt * 16 + g;
            int m = n0 + wn * 32 + nt * 8 + tg * 2;
            size_t off0 = base + (size_t)c * N_TOK + m;
            size_t off1 = base + (size_t)(c + 8) * N_TOK + m;
            float2 x0 = *(const float2*)(x + off0);
            float2 x1 = *(const float2*)(x + off1);
            *(float2*)(out + off0) = make_float2(gam * acc[mt][nt][0] + x0.x,
                                                 gam * acc[mt][nt][1] + x0.y);
            *(float2*)(out + off1) = make_float2(gam * acc[mt][nt][2] + x1.x,
                                                 gam * acc[mt][nt][3] + x1.y);
        }
}

// ---------------- launch -----------------------------------------------------
extern "C" void kernel_launch(void* const* d_in, const int* in_sizes, int n_in,
                              void* d_out, int out_size) {
    const float* x     = (const float*)d_in[0];
    const float* Wq    = (const float*)d_in[1];
    const float* bq    = (const float*)d_in[2];
    const float* uq    = (const float*)d_in[3];
    const float* Wk    = (const float*)d_in[4];
    const float* bk    = (const float*)d_in[5];
    const float* uk    = (const float*)d_in[6];
    const float* Wv    = (const float*)d_in[7];
    const float* bv    = (const float*)d_in[8];
    const float* uv    = (const float*)d_in[9];
    const float* gamma = (const float*)d_in[10];
    float* out = (float*)d_out;

    const int SMEM = 10240 * sizeof(uint32_t);   // 40 KB

    sn_kernel<<<3, 512>>>(Wq, uq, bq, Wk, uk, bk, Wv, uv, bv);
    transpose_kernel<<<dim3(32, 16, BATCH), dim3(32, 8)>>>(x);
    proj_qk_kernel<<<dim3(8, 1, BATCH), 256, SMEM>>>();
    proj_v_kernel<<<dim3(4, 8, BATCH), 256, SMEM>>>();
    qk_kernel<<<dim3(8, 8, BATCH), 256, SMEM>>>();
    softmax_kernel<<<dim3(N_TOK, BATCH), 256>>>();
    av_kernel<<<dim3(4, 8, BATCH), 256, SMEM>>>(x, gamma, out);
}

// round 5
// speedup vs baseline: 2.2128x; 1.1717x over previous
#include <cuda_runtime.h>
#include <cuda_bf16.h>
#include <math.h>
#include <stdint.h>

#define N_TOK 1024
#define C_IN  512
#define CQ    64
#define BATCH 32

// ---------------- scratch (device globals; no allocation allowed) ----------
__device__ __align__(128) __nv_bfloat16 g_Wn_hi[640 * C_IN];   // rows: q 0-63, k 64-127, v 128-639 (K-major)
__device__ __align__(128) __nv_bfloat16 g_Wn_lo[640 * C_IN];
__device__ __align__(128) float g_bias[640];
__device__ __align__(128) __nv_bfloat16 g_xT_hi[(size_t)BATCH * N_TOK * C_IN];  // [b][n][c]
__device__ __align__(128) __nv_bfloat16 g_xT_lo[(size_t)BATCH * N_TOK * C_IN];
__device__ __align__(128) __nv_bfloat16 g_qT_hi[(size_t)BATCH * N_TOK * CQ];    // [b][n][o]
__device__ __align__(128) __nv_bfloat16 g_qT_lo[(size_t)BATCH * N_TOK * CQ];
__device__ __align__(128) __nv_bfloat16 g_kT_hi[(size_t)BATCH * N_TOK * CQ];    // [b][m][o]
__device__ __align__(128) __nv_bfloat16 g_kT_lo[(size_t)BATCH * N_TOK * CQ];
__device__ __align__(128) __nv_bfloat16 g_v_hi [(size_t)BATCH * C_IN * N_TOK];  // [b][c][n]
__device__ __align__(128) __nv_bfloat16 g_v_lo [(size_t)BATCH * C_IN * N_TOK];
__device__ __align__(128) float         g_S    [(size_t)BATCH * N_TOK * N_TOK]; // [b][m][n]
__device__ __align__(128) __nv_bfloat16 g_P_hi [(size_t)BATCH * N_TOK * N_TOK]; // [b][m][n]
__device__ __align__(128) __nv_bfloat16 g_P_lo [(size_t)BATCH * N_TOK * N_TOK];

// ---------------- helpers ----------------------------------------------------
__device__ __forceinline__ uint32_t cvta_smem(const void* p) {
    uint32_t a;
    asm("{ .reg .u64 t; cvta.to.shared.u64 t, %1; cvt.u32.u64 %0, t; }" : "=r"(a) : "l"(p));
    return a;
}
#define CP16(dst, src)  asm volatile("cp.async.cg.shared.global [%0], [%1], 16;" :: "r"(dst), "l"(src) : "memory")
#define CP_COMMIT()     asm volatile("cp.async.commit_group;" ::: "memory")
#define CP_WAIT0()      asm volatile("cp.async.wait_group 0;" ::: "memory")

__device__ __forceinline__ void pack_split2(float a, float b, uint32_t& h, uint32_t& l) {
    __nv_bfloat16 ah = __float2bfloat16(a);
    __nv_bfloat16 bh = __float2bfloat16(b);
    __nv_bfloat16 al = __float2bfloat16(a - __bfloat162float(ah));
    __nv_bfloat16 bl = __float2bfloat16(b - __bfloat162float(bh));
    h = (uint32_t)__bfloat16_as_ushort(ah) | ((uint32_t)__bfloat16_as_ushort(bh) << 16);
    l = (uint32_t)__bfloat16_as_ushort(al) | ((uint32_t)__bfloat16_as_ushort(bl) << 16);
}

__device__ __forceinline__ void mma_bf16(float c[4], const uint32_t a[4], const uint32_t b[2]) {
    asm volatile(
        "mma.sync.aligned.m16n8k16.row.col.f32.bf16.bf16.f32 "
        "{%0,%1,%2,%3}, {%4,%5,%6,%7}, {%8,%9}, {%0,%1,%2,%3};"
        : "+f"(c[0]), "+f"(c[1]), "+f"(c[2]), "+f"(c[3])
        : "r"(a[0]), "r"(a[1]), "r"(a[2]), "r"(a[3]), "r"(b[0]), "r"(b[1]));
}

// ---------------- shared GEMM core ------------------------------------------
// D[128][128] += A[128, K] · B[128, K]^T ; A,B pre-split bf16 hi/lo, K-major.
// 256 threads, 8 warps (2m x 4n), warp tile 64x32. K-chunk 32, double-buffered
// smem via cp.async, ONE __syncthreads per chunk. smem rows padded to 80B.
template<int KT>
__device__ __forceinline__ void gemm_core(
    const __nv_bfloat16* __restrict__ Ah, const __nv_bfloat16* __restrict__ Al, int sA,
    const __nv_bfloat16* __restrict__ Bh, const __nv_bfloat16* __restrict__ Bl, int sB,
    float acc[4][4][4], uint32_t* smp, uint32_t smaddr)
{
    const int tid = threadIdx.x;
    const int lane = tid & 31, wid = tid >> 5;
    const int wm = wid & 1, wn = wid >> 1;
    const int g = lane >> 2, tg = lane & 3;

    // issue copies of one 4x(128x32 bf16) chunk into buffer p
    auto issue = [&](int p, int kt) {
        int k0 = kt * 32;
        uint32_t base = smaddr + (uint32_t)p * 40960u;
#pragma unroll
        for (int t2 = 0; t2 < 8; t2++) {
            int s  = tid + (t2 << 8);          // 0..2047
            int op = s >> 10;                  // 0=A 1=B
            int hf = (s >> 9) & 1;             // 0=hi 1=lo
            int r  = (s >> 2) & 127;
            int sg = s & 3;
            const __nv_bfloat16* src =
                (op ? (hf ? Bl : Bh) + (size_t)r * sB
                    : (hf ? Al : Ah) + (size_t)r * sA) + k0 + sg * 8;
            uint32_t dst = base + (uint32_t)(op * 5120 + hf * 2560 + r * 20 + sg * 4) * 4u;
            CP16(dst, src);
        }
        CP_COMMIT();
    };

    issue(0, 0);
    for (int kt = 0; kt < KT; kt++) {
        int p = kt & 1;
        CP_WAIT0();
        __syncthreads();
        if (kt + 1 < KT) issue(p ^ 1, kt + 1);

        const uint32_t* AHI = smp + p * 10240;
        const uint32_t* ALO = AHI + 2560;
        const uint32_t* BHI = AHI + 5120;
        const uint32_t* BLO = AHI + 7680;
#pragma unroll
        for (int ks = 0; ks < 2; ks++) {
            uint32_t ah[4][4], al[4][4], bh[4][2], bl[4][2];
#pragma unroll
            for (int mt = 0; mt < 4; mt++) {
                int row = wm * 64 + mt * 16 + g;
#pragma unroll
                for (int i = 0; i < 4; i++) {
                    int idx = (row + (i & 1) * 8) * 20 + tg + (i >> 1) * 4 + ks * 8;
                    ah[mt][i] = AHI[idx];
                    al[mt][i] = ALO[idx];
                }
            }
#pragma unroll
            for (int nt = 0; nt < 4; nt++) {
                int row = wn * 32 + nt * 8 + g;
#pragma unroll
                for (int j = 0; j < 2; j++) {
                    int idx = row * 20 + tg + j * 4 + ks * 8;
                    bh[nt][j] = BHI[idx];
                    bl[nt][j] = BLO[idx];
                }
            }
#pragma unroll
            for (int mt = 0; mt < 4; mt++)
#pragma unroll
                for (int nt = 0; nt < 4; nt++) {
                    mma_bf16(acc[mt][nt], ah[mt], bh[nt]);
                    mma_bf16(acc[mt][nt], ah[mt], bl[nt]);
                    mma_bf16(acc[mt][nt], al[mt], bh[nt]);
                }
        }
    }
}

// ---------------- spectral norm ---------------------------------------------
__global__ void sn_kernel(const float* __restrict__ Wq, const float* __restrict__ uq, const float* __restrict__ bq,
                          const float* __restrict__ Wk, const float* __restrict__ uk, const float* __restrict__ bk,
                          const float* __restrict__ Wv, const float* __restrict__ uv, const float* __restrict__ bv) {
    const float* W; const float* u; const float* bias; int out; int dst;
    if (blockIdx.x == 0)      { W = Wq; u = uq; bias = bq; out = CQ;   dst = 0;   }
    else if (blockIdx.x == 1) { W = Wk; u = uk; bias = bk; out = CQ;   dst = 64;  }
    else                      { W = Wv; u = uv; bias = bv; out = C_IN; dst = 128; }

    __shared__ float su[C_IN];
    __shared__ float sv[C_IN];
    __shared__ float red[512];
    int tid = threadIdx.x;

    if (tid < out) { su[tid] = u[tid]; g_bias[dst + tid] = bias[tid]; }
    __syncthreads();

    float t = 0.f;
    for (int i = 0; i < out; i++) t += W[i * C_IN + tid] * su[i];
    red[tid] = t * t;
    __syncthreads();
    for (int s = 256; s > 0; s >>= 1) { if (tid < s) red[tid] += red[tid + s]; __syncthreads(); }
    float nv = sqrtf(red[0]);
    sv[tid] = t / nv;
    __syncthreads();

    float p = 0.f;
    for (int i = tid; i < out; i += blockDim.x) {
        float r = 0.f;
        for (int j = 0; j < C_IN; j++) r += W[i * C_IN + j] * sv[j];
        p += r * r;
    }
    red[tid] = p;
    __syncthreads();
    for (int s = 256; s > 0; s >>= 1) { if (tid < s) red[tid] += red[tid + s]; __syncthreads(); }
    float inv_sigma = rsqrtf(red[0]);

    for (int e = tid; e < out * C_IN; e += blockDim.x) {
        float val = W[e] * inv_sigma;
        __nv_bfloat16 h = __float2bfloat16(val);
        g_Wn_hi[(size_t)dst * C_IN + e] = h;
        g_Wn_lo[(size_t)dst * C_IN + e] = __float2bfloat16(val - __bfloat162float(h));
    }
}

// ---------------- x transpose + split: xT_hi/lo[b][n][c] --------------------
__global__ void transpose_kernel(const float* __restrict__ x) {
    __shared__ float t[32][33];
    int b = blockIdx.z, c0 = blockIdx.y * 32, n0 = blockIdx.x * 32;
    int tx = threadIdx.x, ty = threadIdx.y;
    const float* src = x + (size_t)b * C_IN * N_TOK;
    size_t dbase = (size_t)b * N_TOK * C_IN;
#pragma unroll
    for (int i = ty; i < 32; i += 8) t[i][tx] = src[(size_t)(c0 + i) * N_TOK + n0 + tx];
    __syncthreads();
#pragma unroll
    for (int i = ty; i < 32; i += 8) {
        float val = t[tx][i];
        __nv_bfloat16 h = __float2bfloat16(val);
        size_t off = dbase + (size_t)(n0 + i) * C_IN + c0 + tx;
        g_xT_hi[off] = h;
        g_xT_lo[off] = __float2bfloat16(val - __bfloat162float(h));
    }
}

// ---------------- proj_qk: D[n][o] -> qT/kT hi/lo ---------------------------
__global__ void __launch_bounds__(256) proj_qk_kernel() {
    extern __shared__ uint32_t sm[];
    uint32_t sma = cvta_smem(sm);
    int b = blockIdx.z, m0 = blockIdx.x * 128;
    float acc[4][4][4] = {};
    const __nv_bfloat16* Ah = g_xT_hi + ((size_t)b * N_TOK + m0) * C_IN;
    const __nv_bfloat16* Al = g_xT_lo + ((size_t)b * N_TOK + m0) * C_IN;
    gemm_core<16>(Ah, Al, C_IN, g_Wn_hi, g_Wn_lo, C_IN, acc, sm, sma);

    int tid = threadIdx.x, lane = tid & 31, wid = tid >> 5;
    int wm = wid & 1, wn = wid >> 1, g = lane >> 2, tg = lane & 3;
#pragma unroll
    for (int mt = 0; mt < 4; mt++)
#pragma unroll
        for (int nt = 0; nt < 4; nt++) {
            int r = m0 + wm * 64 + mt * 16 + g;
            int o = wn * 32 + nt * 8 + tg * 2;
            float b0 = g_bias[o], b1 = g_bias[o + 1];
            int oo = (o < 64) ? o : (o - 64);
            uint32_t* hi = (uint32_t*)((o < 64) ? g_qT_hi : g_kT_hi) + ((size_t)b * N_TOK) * 32;
            uint32_t* lo = (uint32_t*)((o < 64) ? g_qT_lo : g_kT_lo) + ((size_t)b * N_TOK) * 32;
            uint32_t h, l;
            pack_split2(acc[mt][nt][0] + b0, acc[mt][nt][1] + b1, h, l);
            hi[(size_t)r * 32 + (oo >> 1)] = h;
            lo[(size_t)r * 32 + (oo >> 1)] = l;
            pack_split2(acc[mt][nt][2] + b0, acc[mt][nt][3] + b1, h, l);
            hi[(size_t)(r + 8) * 32 + (oo >> 1)] = h;
            lo[(size_t)(r + 8) * 32 + (oo >> 1)] = l;
        }
}

// ---------------- proj_v: D[c][n] -> v hi/lo --------------------------------
__global__ void __launch_bounds__(256) proj_v_kernel() {
    extern __shared__ uint32_t sm[];
    uint32_t sma = cvta_smem(sm);
    int b = blockIdx.z, m0 = blockIdx.x * 128, n0 = blockIdx.y * 128;  // c, n
    float acc[4][4][4] = {};
    gemm_core<16>(g_Wn_hi + (size_t)(128 + m0) * C_IN, g_Wn_lo + (size_t)(128 + m0) * C_IN, C_IN,
                  g_xT_hi + ((size_t)b * N_TOK + n0) * C_IN, g_xT_lo + ((size_t)b * N_TOK + n0) * C_IN, C_IN,
                  acc, sm, sma);

    int tid = threadIdx.x, lane = tid & 31, wid = tid >> 5;
    int wm = wid & 1, wn = wid >> 1, g = lane >> 2, tg = lane & 3;
    uint32_t* vh = (uint32_t*)g_v_hi + (size_t)b * C_IN * 512;
    uint32_t* vl = (uint32_t*)g_v_lo + (size_t)b * C_IN * 512;
#pragma unroll
    for (int mt = 0; mt < 4; mt++)
#pragma unroll
        for (int nt = 0; nt < 4; nt++) {
            int c = m0 + wm * 64 + mt * 16 + g;
            int n = n0 + wn * 32 + nt * 8 + tg * 2;
            float b0 = g_bias[128 + c], b1 = g_bias[128 + c + 8];
            uint32_t h, l;
            pack_split2(acc[mt][nt][0] + b0, acc[mt][nt][1] + b0, h, l);
            vh[(size_t)c * 512 + (n >> 1)] = h;
            vl[(size_t)c * 512 + (n >> 1)] = l;
            pack_split2(acc[mt][nt][2] + b1, acc[mt][nt][3] + b1, h, l);
            vh[(size_t)(c + 8) * 512 + (n >> 1)] = h;
            vl[(size_t)(c + 8) * 512 + (n >> 1)] = l;
        }
}

// ---------------- qk: S[m][n] fp32 ------------------------------------------
__global__ void __launch_bounds__(256) qk_kernel() {
    extern __shared__ uint32_t sm[];
    uint32_t sma = cvta_smem(sm);
    int b = blockIdx.z, m0 = blockIdx.x * 128, n0 = blockIdx.y * 128;
    float acc[4][4][4] = {};
    gemm_core<2>(g_kT_hi + ((size_t)b * N_TOK + m0) * CQ, g_kT_lo + ((size_t)b * N_TOK + m0) * CQ, CQ,
                 g_qT_hi + ((size_t)b * N_TOK + n0) * CQ, g_qT_lo + ((size_t)b * N_TOK + n0) * CQ, CQ,
                 acc, sm, sma);

    int tid = threadIdx.x, lane = tid & 31, wid = tid >> 5;
    int wm = wid & 1, wn = wid >> 1, g = lane >> 2, tg = lane & 3;
    float* Sb = g_S + (size_t)b * N_TOK * N_TOK;
#pragma unroll
    for (int mt = 0; mt < 4; mt++)
#pragma unroll
        for (int nt = 0; nt < 4; nt++) {
            int m = m0 + wm * 64 + mt * 16 + g;
            int n = n0 + wn * 32 + nt * 8 + tg * 2;
            *(float2*)(Sb + (size_t)m * N_TOK + n)       = make_float2(acc[mt][nt][0], acc[mt][nt][1]);
            *(float2*)(Sb + (size_t)(m + 8) * N_TOK + n) = make_float2(acc[mt][nt][2], acc[mt][nt][3]);
        }
}

// ---------------- row softmax -> P hi/lo ------------------------------------
__global__ void __launch_bounds__(256) softmax_kernel() {
    int b = blockIdx.y, m = blockIdx.x;
    const float* row = g_S + ((size_t)b * N_TOK + m) * N_TOK;
    int tid = threadIdx.x;
    __shared__ float smr[8];

    float4 v = ((const float4*)row)[tid];
    float mx = fmaxf(fmaxf(v.x, v.y), fmaxf(v.z, v.w));
#pragma unroll
    for (int s = 16; s; s >>= 1) mx = fmaxf(mx, __shfl_xor_sync(0xffffffffu, mx, s));
    if ((tid & 31) == 0) smr[tid >> 5] = mx;
    __syncthreads();
    mx = smr[0];
#pragma unroll
    for (int w = 1; w < 8; w++) mx = fmaxf(mx, smr[w]);
    __syncthreads();

    v.x = __expf(v.x - mx); v.y = __expf(v.y - mx);
    v.z = __expf(v.z - mx); v.w = __expf(v.w - mx);
    float s4 = v.x + v.y + v.z + v.w;
#pragma unroll
    for (int s = 16; s; s >>= 1) s4 += __shfl_xor_sync(0xffffffffu, s4, s);
    if ((tid & 31) == 0) smr[tid >> 5] = s4;
    __syncthreads();
    float tot = 0.f;
#pragma unroll
    for (int w = 0; w < 8; w++) tot += smr[w];
    float inv = 1.f / tot;
    v.x *= inv; v.y *= inv; v.z *= inv; v.w *= inv;

    uint32_t h0, l0, h1, l1;
    pack_split2(v.x, v.y, h0, l0);
    pack_split2(v.z, v.w, h1, l1);
    size_t ro = ((size_t)b * N_TOK + m) * 512;
    ((uint2*)((uint32_t*)g_P_hi + ro))[tid] = make_uint2(h0, h1);
    ((uint2*)((uint32_t*)g_P_lo + ro))[tid] = make_uint2(l0, l1);
}

// ---------------- av: out[c][m] = gamma*(v · P^T) + x -----------------------
__global__ void __launch_bounds__(256) av_kernel(const float* __restrict__ x,
                                                 const float* __restrict__ gamma_p,
                                                 float* __restrict__ out) {
    extern __shared__ uint32_t sm[];
    uint32_t sma = cvta_smem(sm);
    int b = blockIdx.z, m0 = blockIdx.x * 128, n0 = blockIdx.y * 128;  // c, m
    float acc[4][4][4] = {};
    gemm_core<32>(g_v_hi + ((size_t)b * C_IN + m0) * N_TOK, g_v_lo + ((size_t)b * C_IN + m0) * N_TOK, N_TOK,
                  g_P_hi + ((size_t)b * N_TOK + n0) * N_TOK, g_P_lo + ((size_t)b * N_TOK + n0) * N_TOK, N_TOK,
                  acc, sm, sma);

    int tid = threadIdx.x, lane = tid & 31, wid = tid >> 5;
    int wm = wid & 1, wn = wid >> 1, g = lane >> 2, tg = lane & 3;
    float gam = *gamma_p;
    size_t base = (size_t)b * C_IN * N_TOK;
#pragma unroll
    for (int mt = 0; mt < 4; mt++)
#pragma unroll
        for (int nt = 0; nt < 4; nt++) {
            int c = m0 + wm * 64 + mt * 16 + g;
            int m = n0 + wn * 32 + nt * 8 + tg * 2;
            size_t off0 = base + (size_t)c * N_TOK + m;
            size_t off1 = base + (size_t)(c + 8) * N_TOK + m;
            float2 x0 = *(const float2*)(x + off0);
            float2 x1 = *(const float2*)(x + off1);
            *(float2*)(out + off0) = make_float2(gam * acc[mt][nt][0] + x0.x,
                                                 gam * acc[mt][nt][1] + x0.y);
            *(float2*)(out + off1) = make_float2(gam * acc[mt][nt][2] + x1.x,
                                                 gam * acc[mt][nt][3] + x1.y);
        }
}

// ---------------- launch -----------------------------------------------------
extern "C" void kernel_launch(void* const* d_in, const int* in_sizes, int n_in,
                              void* d_out, int out_size) {
    const float* x     = (const float*)d_in[0];
    const float* Wq    = (const float*)d_in[1];
    const float* bq    = (const float*)d_in[2];
    const float* uq    = (const float*)d_in[3];
    const float* Wk    = (const float*)d_in[4];
    const float* bk    = (const float*)d_in[5];
    const float* uk    = (const float*)d_in[6];
    const float* Wv    = (const float*)d_in[7];
    const float* bv    = (const float*)d_in[8];
    const float* uv    = (const float*)d_in[9];
    const float* gamma = (const float*)d_in[10];
    float* out = (float*)d_out;

    const int SMEM = 81920;   // 2 x 40KB double buffer

    static int configured = 0;
    if (!configured) {
        cudaFuncSetAttribute(proj_qk_kernel, cudaFuncAttributeMaxDynamicSharedMemorySize, SMEM);
        cudaFuncSetAttribute(proj_v_kernel,  cudaFuncAttributeMaxDynamicSharedMemorySize, SMEM);
        cudaFuncSetAttribute(qk_kernel,      cudaFuncAttributeMaxDynamicSharedMemorySize, SMEM);
        cudaFuncSetAttribute(av_kernel,      cudaFuncAttributeMaxDynamicSharedMemorySize, SMEM);
        configured = 1;
    }

    sn_kernel<<<3, 512>>>(Wq, uq, bq, Wk, uk, bk, Wv, uv, bv);
    transpose_kernel<<<dim3(32, 16, BATCH), dim3(32, 8)>>>(x);
    proj_qk_kernel<<<dim3(8, 1, BATCH), 256, SMEM>>>();
    proj_v_kernel<<<dim3(4, 8, BATCH), 256, SMEM>>>();
    qk_kernel<<<dim3(8, 8, BATCH), 256, SMEM>>>();
    softmax_kernel<<<dim3(N_TOK, BATCH), 256>>>();
    av_kernel<<<dim3(4, 8, BATCH), 256, SMEM>>>(x, gamma, out);
}

// round 6
// speedup vs baseline: 2.4937x; 1.1270x over previous
#include <cuda_runtime.h>
#include <cuda_bf16.h>
#include <math.h>
#include <stdint.h>

#define N_TOK 1024
#define C_IN  512
#define CQ    64
#define BATCH 32

// ---------------- scratch (device globals; no allocation allowed) ----------
__device__ __align__(128) __nv_bfloat16 g_Wn_hi[640 * C_IN];   // rows: q 0-63, k 64-127, v 128-639 (K-major)
__device__ __align__(128) __nv_bfloat16 g_Wn_lo[640 * C_IN];
__device__ __align__(128) float g_bias[640];
__device__ __align__(128) __nv_bfloat16 g_xT_hi[(size_t)BATCH * N_TOK * C_IN];  // [b][n][c]
__device__ __align__(128) __nv_bfloat16 g_xT_lo[(size_t)BATCH * N_TOK * C_IN];
__device__ __align__(128) __nv_bfloat16 g_qT_hi[(size_t)BATCH * N_TOK * CQ];    // [b][n][o]
__device__ __align__(128) __nv_bfloat16 g_qT_lo[(size_t)BATCH * N_TOK * CQ];
__device__ __align__(128) __nv_bfloat16 g_kT_hi[(size_t)BATCH * N_TOK * CQ];    // [b][m][o]
__device__ __align__(128) __nv_bfloat16 g_kT_lo[(size_t)BATCH * N_TOK * CQ];
__device__ __align__(128) __nv_bfloat16 g_v_hi [(size_t)BATCH * C_IN * N_TOK];  // [b][c][n]
__device__ __align__(128) __nv_bfloat16 g_v_lo [(size_t)BATCH * C_IN * N_TOK];
__device__ __align__(128) float         g_S    [(size_t)BATCH * N_TOK * N_TOK]; // [b][m][n]
__device__ __align__(128) __nv_bfloat16 g_P_hi [(size_t)BATCH * N_TOK * N_TOK]; // [b][m][n]
__device__ __align__(128) __nv_bfloat16 g_P_lo [(size_t)BATCH * N_TOK * N_TOK];

// ---------------- helpers ----------------------------------------------------
__device__ __forceinline__ uint32_t cvta_smem(const void* p) {
    uint32_t a;
    asm("{ .reg .u64 t; cvta.to.shared.u64 t, %1; cvt.u32.u64 %0, t; }" : "=r"(a) : "l"(p));
    return a;
}
#define CP16(dst, src)  asm volatile("cp.async.cg.shared.global [%0], [%1], 16;" :: "r"(dst), "l"(src) : "memory")
#define CP_COMMIT()     asm volatile("cp.async.commit_group;" ::: "memory")
#define CP_WAIT0()      asm volatile("cp.async.wait_group 0;" ::: "memory")
#define LDM4(r, a) \
    asm volatile("ldmatrix.sync.aligned.m8n8.x4.shared.b16 {%0,%1,%2,%3}, [%4];" \
        : "=r"((r)[0]), "=r"((r)[1]), "=r"((r)[2]), "=r"((r)[3]) : "r"(a))

__device__ __forceinline__ void pack_split2(float a, float b, uint32_t& h, uint32_t& l) {
    __nv_bfloat16 ah = __float2bfloat16(a);
    __nv_bfloat16 bh = __float2bfloat16(b);
    __nv_bfloat16 al = __float2bfloat16(a - __bfloat162float(ah));
    __nv_bfloat16 bl = __float2bfloat16(b - __bfloat162float(bh));
    h = (uint32_t)__bfloat16_as_ushort(ah) | ((uint32_t)__bfloat16_as_ushort(bh) << 16);
    l = (uint32_t)__bfloat16_as_ushort(al) | ((uint32_t)__bfloat16_as_ushort(bl) << 16);
}

__device__ __forceinline__ void mma_bf16(float c[4], const uint32_t a[4], const uint32_t b[2]) {
    asm volatile(
        "mma.sync.aligned.m16n8k16.row.col.f32.bf16.bf16.f32 "
        "{%0,%1,%2,%3}, {%4,%5,%6,%7}, {%8,%9}, {%0,%1,%2,%3};"
        : "+f"(c[0]), "+f"(c[1]), "+f"(c[2]), "+f"(c[3])
        : "r"(a[0]), "r"(a[1]), "r"(a[2]), "r"(a[3]), "r"(b[0]), "r"(b[1]));
}

// ---------------- shared GEMM core ------------------------------------------
// D[128][128] += A[128, K] · B[128, K]^T ; A,B pre-split bf16 hi/lo, K-major.
// 256 threads, 8 warps (2m x 4n), warp tile 64x32. K-chunk 32, double-buffered
// cp.async smem, ONE __syncthreads per chunk, ldmatrix fragment loads.
// smem layout per buffer (10240 u32): AHI[128x20] ALO BHI BLO (80B rows).
template<int KT>
__device__ __forceinline__ void gemm_core(
    const __nv_bfloat16* __restrict__ Ah, const __nv_bfloat16* __restrict__ Al, int sA,
    const __nv_bfloat16* __restrict__ Bh, const __nv_bfloat16* __restrict__ Bl, int sB,
    float acc[4][4][4], uint32_t smaddr)
{
    const int tid = threadIdx.x;
    const int lane = tid & 31, wid = tid >> 5;
    const int wm = wid & 1, wn = wid >> 1;

    // ldmatrix per-lane addressing
    const int arow = lane & 15, akh = lane >> 4;                 // A: rows 0-15, k-half
    const int brow = (lane & 7) + ((lane >> 4) & 1) * 8;         // B: covers 16 n-rows
    const int bkh  = (lane >> 3) & 1;
    const uint32_t aB = smaddr + (uint32_t)((wm * 64 + arow) * 80 + akh * 16);
    const uint32_t bB = smaddr + 20480u + (uint32_t)((wn * 32 + brow) * 80 + bkh * 16);

    auto issue = [&](int p, int kt) {
        int k0 = kt * 32;
        uint32_t base = smaddr + (uint32_t)p * 40960u;
#pragma unroll
        for (int t2 = 0; t2 < 8; t2++) {
            int s  = tid + (t2 << 8);          // 0..2047
            int op = s >> 10;                  // 0=A 1=B
            int hf = (s >> 9) & 1;             // 0=hi 1=lo
            int r  = (s >> 2) & 127;
            int sg = s & 3;
            const __nv_bfloat16* src =
                (op ? (hf ? Bl : Bh) + (size_t)r * sB
                    : (hf ? Al : Ah) + (size_t)r * sA) + k0 + sg * 8;
            uint32_t dst = base + (uint32_t)(op * 20480 + hf * 10240 + r * 80 + sg * 16);
            CP16(dst, src);
        }
        CP_COMMIT();
    };

    issue(0, 0);
    for (int kt = 0; kt < KT; kt++) {
        int p = kt & 1;
        CP_WAIT0();
        __syncthreads();
        if (kt + 1 < KT) issue(p ^ 1, kt + 1);

        uint32_t poff = (uint32_t)p * 40960u;
#pragma unroll
        for (int ks = 0; ks < 2; ks++) {
            uint32_t ah[4][4], al[4][4], bp[2][4], blp[2][4];
#pragma unroll
            for (int mt = 0; mt < 4; mt++) {
                uint32_t a = aB + poff + (uint32_t)(mt * 1280 + ks * 32);
                LDM4(ah[mt], a);
                LDM4(al[mt], a + 10240u);
            }
#pragma unroll
            for (int pr = 0; pr < 2; pr++) {
                uint32_t a = bB + poff + (uint32_t)(pr * 1280 + ks * 32);
                LDM4(bp[pr], a);
                LDM4(blp[pr], a + 10240u);
            }
#pragma unroll
            for (int mt = 0; mt < 4; mt++)
#pragma unroll
                for (int nt = 0; nt < 4; nt++) {
                    const uint32_t* bh = &bp[nt >> 1][(nt & 1) * 2];
                    const uint32_t* bl = &blp[nt >> 1][(nt & 1) * 2];
                    mma_bf16(acc[mt][nt], ah[mt], bh);
                    mma_bf16(acc[mt][nt], ah[mt], bl);
                    mma_bf16(acc[mt][nt], al[mt], bh);
                }
        }
    }
}

// ---------------- spectral norm ---------------------------------------------
__global__ void sn_kernel(const float* __restrict__ Wq, const float* __restrict__ uq, const float* __restrict__ bq,
                          const float* __restrict__ Wk, const float* __restrict__ uk, const float* __restrict__ bk,
                          const float* __restrict__ Wv, const float* __restrict__ uv, const float* __restrict__ bv) {
    const float* W; const float* u; const float* bias; int out; int dst;
    if (blockIdx.x == 0)      { W = Wq; u = uq; bias = bq; out = CQ;   dst = 0;   }
    else if (blockIdx.x == 1) { W = Wk; u = uk; bias = bk; out = CQ;   dst = 64;  }
    else                      { W = Wv; u = uv; bias = bv; out = C_IN; dst = 128; }

    __shared__ float su[C_IN];
    __shared__ float sv[C_IN];
    __shared__ float red[512];
    int tid = threadIdx.x;

    if (tid < out) { su[tid] = u[tid]; g_bias[dst + tid] = bias[tid]; }
    __syncthreads();

    float t = 0.f;
    for (int i = 0; i < out; i++) t += W[i * C_IN + tid] * su[i];
    red[tid] = t * t;
    __syncthreads();
    for (int s = 256; s > 0; s >>= 1) { if (tid < s) red[tid] += red[tid + s]; __syncthreads(); }
    float nv = sqrtf(red[0]);
    sv[tid] = t / nv;
    __syncthreads();

    float p = 0.f;
    for (int i = tid; i < out; i += blockDim.x) {
        float r = 0.f;
        for (int j = 0; j < C_IN; j++) r += W[i * C_IN + j] * sv[j];
        p += r * r;
    }
    red[tid] = p;
    __syncthreads();
    for (int s = 256; s > 0; s >>= 1) { if (tid < s) red[tid] += red[tid + s]; __syncthreads(); }
    float inv_sigma = rsqrtf(red[0]);

    for (int e = tid; e < out * C_IN; e += blockDim.x) {
        float val = W[e] * inv_sigma;
        __nv_bfloat16 h = __float2bfloat16(val);
        g_Wn_hi[(size_t)dst * C_IN + e] = h;
        g_Wn_lo[(size_t)dst * C_IN + e] = __float2bfloat16(val - __bfloat162float(h));
    }
}

// ---------------- x transpose + split: xT_hi/lo[b][n][c] --------------------
__global__ void transpose_kernel(const float* __restrict__ x) {
    __shared__ float t[32][33];
    int b = blockIdx.z, c0 = blockIdx.y * 32, n0 = blockIdx.x * 32;
    int tx = threadIdx.x, ty = threadIdx.y;
    const float* src = x + (size_t)b * C_IN * N_TOK;
    size_t dbase = (size_t)b * N_TOK * C_IN;
#pragma unroll
    for (int i = ty; i < 32; i += 8) t[i][tx] = src[(size_t)(c0 + i) * N_TOK + n0 + tx];
    __syncthreads();
#pragma unroll
    for (int i = ty; i < 32; i += 8) {
        float val = t[tx][i];
        __nv_bfloat16 h = __float2bfloat16(val);
        size_t off = dbase + (size_t)(n0 + i) * C_IN + c0 + tx;
        g_xT_hi[off] = h;
        g_xT_lo[off] = __float2bfloat16(val - __bfloat162float(h));
    }
}

// ---------------- proj_qk: D[n][o] -> qT/kT hi/lo ---------------------------
__global__ void __launch_bounds__(256, 2) proj_qk_kernel() {
    extern __shared__ uint32_t sm[];
    uint32_t sma = cvta_smem(sm);
    int b = blockIdx.z, m0 = blockIdx.x * 128;
    float acc[4][4][4] = {};
    gemm_core<16>(g_xT_hi + ((size_t)b * N_TOK + m0) * C_IN,
                  g_xT_lo + ((size_t)b * N_TOK + m0) * C_IN, C_IN,
                  g_Wn_hi, g_Wn_lo, C_IN, acc, sma);

    int tid = threadIdx.x, lane = tid & 31, wid = tid >> 5;
    int wm = wid & 1, wn = wid >> 1, g = lane >> 2, tg = lane & 3;
#pragma unroll
    for (int mt = 0; mt < 4; mt++)
#pragma unroll
        for (int nt = 0; nt < 4; nt++) {
            int r = m0 + wm * 64 + mt * 16 + g;
            int o = wn * 32 + nt * 8 + tg * 2;
            float b0 = g_bias[o], b1 = g_bias[o + 1];
            int oo = (o < 64) ? o : (o - 64);
            uint32_t* hi = (uint32_t*)((o < 64) ? g_qT_hi : g_kT_hi) + ((size_t)b * N_TOK) * 32;
            uint32_t* lo = (uint32_t*)((o < 64) ? g_qT_lo : g_kT_lo) + ((size_t)b * N_TOK) * 32;
            uint32_t h, l;
            pack_split2(acc[mt][nt][0] + b0, acc[mt][nt][1] + b1, h, l);
            hi[(size_t)r * 32 + (oo >> 1)] = h;
            lo[(size_t)r * 32 + (oo >> 1)] = l;
            pack_split2(acc[mt][nt][2] + b0, acc[mt][nt][3] + b1, h, l);
            hi[(size_t)(r + 8) * 32 + (oo >> 1)] = h;
            lo[(size_t)(r + 8) * 32 + (oo >> 1)] = l;
        }
}

// ---------------- proj_v: D[c][n] -> v hi/lo --------------------------------
__global__ void __launch_bounds__(256, 2) proj_v_kernel() {
    extern __shared__ uint32_t sm[];
    uint32_t sma = cvta_smem(sm);
    int b = blockIdx.z, m0 = blockIdx.x * 128, n0 = blockIdx.y * 128;  // c, n
    float acc[4][4][4] = {};
    gemm_core<16>(g_Wn_hi + (size_t)(128 + m0) * C_IN, g_Wn_lo + (size_t)(128 + m0) * C_IN, C_IN,
                  g_xT_hi + ((size_t)b * N_TOK + n0) * C_IN, g_xT_lo + ((size_t)b * N_TOK + n0) * C_IN, C_IN,
                  acc, sma);

    int tid = threadIdx.x, lane = tid & 31, wid = tid >> 5;
    int wm = wid & 1, wn = wid >> 1, g = lane >> 2, tg = lane & 3;
    uint32_t* vh = (uint32_t*)g_v_hi + (size_t)b * C_IN * 512;
    uint32_t* vl = (uint32_t*)g_v_lo + (size_t)b * C_IN * 512;
#pragma unroll
    for (int mt = 0; mt < 4; mt++)
#pragma unroll
        for (int nt = 0; nt < 4; nt++) {
            int c = m0 + wm * 64 + mt * 16 + g;
            int n = n0 + wn * 32 + nt * 8 + tg * 2;
            float b0 = g_bias[128 + c], b1 = g_bias[128 + c + 8];
            uint32_t h, l;
            pack_split2(acc[mt][nt][0] + b0, acc[mt][nt][1] + b0, h, l);
            vh[(size_t)c * 512 + (n >> 1)] = h;
            vl[(size_t)c * 512 + (n >> 1)] = l;
            pack_split2(acc[mt][nt][2] + b1, acc[mt][nt][3] + b1, h, l);
            vh[(size_t)(c + 8) * 512 + (n >> 1)] = h;
            vl[(size_t)(c + 8) * 512 + (n >> 1)] = l;
        }
}

// ---------------- qk: S[m][n] fp32 ------------------------------------------
__global__ void __launch_bounds__(256, 2) qk_kernel() {
    extern __shared__ uint32_t sm[];
    uint32_t sma = cvta_smem(sm);
    int b = blockIdx.z, m0 = blockIdx.x * 128, n0 = blockIdx.y * 128;
    float acc[4][4][4] = {};
    gemm_core<2>(g_kT_hi + ((size_t)b * N_TOK + m0) * CQ, g_kT_lo + ((size_t)b * N_TOK + m0) * CQ, CQ,
                 g_qT_hi + ((size_t)b * N_TOK + n0) * CQ, g_qT_lo + ((size_t)b * N_TOK + n0) * CQ, CQ,
                 acc, sma);

    int tid = threadIdx.x, lane = tid & 31, wid = tid >> 5;
    int wm = wid & 1, wn = wid >> 1, g = lane >> 2, tg = lane & 3;
    float* Sb = g_S + (size_t)b * N_TOK * N_TOK;
#pragma unroll
    for (int mt = 0; mt < 4; mt++)
#pragma unroll
        for (int nt = 0; nt < 4; nt++) {
            int m = m0 + wm * 64 + mt * 16 + g;
            int n = n0 + wn * 32 + nt * 8 + tg * 2;
            *(float2*)(Sb + (size_t)m * N_TOK + n)       = make_float2(acc[mt][nt][0], acc[mt][nt][1]);
            *(float2*)(Sb + (size_t)(m + 8) * N_TOK + n) = make_float2(acc[mt][nt][2], acc[mt][nt][3]);
        }
}

// ---------------- row softmax -> P hi/lo ------------------------------------
__global__ void __launch_bounds__(256) softmax_kernel() {
    int b = blockIdx.y, m = blockIdx.x;
    const float* row = g_S + ((size_t)b * N_TOK + m) * N_TOK;
    int tid = threadIdx.x;
    __shared__ float smr[8];

    float4 v = ((const float4*)row)[tid];
    float mx = fmaxf(fmaxf(v.x, v.y), fmaxf(v.z, v.w));
#pragma unroll
    for (int s = 16; s; s >>= 1) mx = fmaxf(mx, __shfl_xor_sync(0xffffffffu, mx, s));
    if ((tid & 31) == 0) smr[tid >> 5] = mx;
    __syncthreads();
    mx = smr[0];
#pragma unroll
    for (int w = 1; w < 8; w++) mx = fmaxf(mx, smr[w]);
    __syncthreads();

    v.x = __expf(v.x - mx); v.y = __expf(v.y - mx);
    v.z = __expf(v.z - mx); v.w = __expf(v.w - mx);
    float s4 = v.x + v.y + v.z + v.w;
#pragma unroll
    for (int s = 16; s; s >>= 1) s4 += __shfl_xor_sync(0xffffffffu, s4, s);
    if ((tid & 31) == 0) smr[tid >> 5] = s4;
    __syncthreads();
    float tot = 0.f;
#pragma unroll
    for (int w = 0; w < 8; w++) tot += smr[w];
    float inv = 1.f / tot;
    v.x *= inv; v.y *= inv; v.z *= inv; v.w *= inv;

    uint32_t h0, l0, h1, l1;
    pack_split2(v.x, v.y, h0, l0);
    pack_split2(v.z, v.w, h1, l1);
    size_t ro = ((size_t)b * N_TOK + m) * 512;
    ((uint2*)((uint32_t*)g_P_hi + ro))[tid] = make_uint2(h0, h1);
    ((uint2*)((uint32_t*)g_P_lo + ro))[tid] = make_uint2(l0, l1);
}

// ---------------- av: out[c][m] = gamma*(v · P^T) + x -----------------------
__global__ void __launch_bounds__(256, 2) av_kernel(const float* __restrict__ x,
                                                    const float* __restrict__ gamma_p,
                                                    float* __restrict__ out) {
    extern __shared__ uint32_t sm[];
    uint32_t sma = cvta_smem(sm);
    int b = blockIdx.z, m0 = blockIdx.x * 128, n0 = blockIdx.y * 128;  // c, m
    float acc[4][4][4] = {};
    gemm_core<32>(g_v_hi + ((size_t)b * C_IN + m0) * N_TOK, g_v_lo + ((size_t)b * C_IN + m0) * N_TOK, N_TOK,
                  g_P_hi + ((size_t)b * N_TOK + n0) * N_TOK, g_P_lo + ((size_t)b * N_TOK + n0) * N_TOK, N_TOK,
                  acc, sma);

    int tid = threadIdx.x, lane = tid & 31, wid = tid >> 5;
    int wm = wid & 1, wn = wid >> 1, g = lane >> 2, tg = lane & 3;
    float gam = *gamma_p;
    size_t base = (size_t)b * C_IN * N_TOK;
#pragma unroll
    for (int mt = 0; mt < 4; mt++)
#pragma unroll
        for (int nt = 0; nt < 4; nt++) {
            int c = m0 + wm * 64 + mt * 16 + g;
            int m = n0 + wn * 32 + nt * 8 + tg * 2;
            size_t off0 = base + (size_t)c * N_TOK + m;
            size_t off1 = base + (size_t)(c + 8) * N_TOK + m;
            float2 x0 = *(const float2*)(x + off0);
            float2 x1 = *(const float2*)(x + off1);
            *(float2*)(out + off0) = make_float2(gam * acc[mt][nt][0] + x0.x,
                                                 gam * acc[mt][nt][1] + x0.y);
            *(float2*)(out + off1) = make_float2(gam * acc[mt][nt][2] + x1.x,
                                                 gam * acc[mt][nt][3] + x1.y);
        }
}

// ---------------- launch -----------------------------------------------------
extern "C" void kernel_launch(void* const* d_in, const int* in_sizes, int n_in,
                              void* d_out, int out_size) {
    const float* x     = (const float*)d_in[0];
    const float* Wq    = (const float*)d_in[1];
    const float* bq    = (const float*)d_in[2];
    const float* uq    = (const float*)d_in[3];
    const float* Wk    = (const float*)d_in[4];
    const float* bk    = (const float*)d_in[5];
    const float* uk    = (const float*)d_in[6];
    const float* Wv    = (const float*)d_in[7];
    const float* bv    = (const float*)d_in[8];
    const float* uv    = (const float*)d_in[9];
    const float* gamma = (const float*)d_in[10];
    float* out = (float*)d_out;

    const int SMEM = 81920;   // 2 x 40KB double buffer

    static int configured = 0;
    if (!configured) {
        cudaFuncSetAttribute(proj_qk_kernel, cudaFuncAttributeMaxDynamicSharedMemorySize, SMEM);
        cudaFuncSetAttribute(proj_v_kernel,  cudaFuncAttributeMaxDynamicSharedMemorySize, SMEM);
        cudaFuncSetAttribute(qk_kernel,      cudaFuncAttributeMaxDynamicSharedMemorySize, SMEM);
        cudaFuncSetAttribute(av_kernel,      cudaFuncAttributeMaxDynamicSharedMemorySize, SMEM);
        configured = 1;
    }

    sn_kernel<<<3, 512>>>(Wq, uq, bq, Wk, uk, bk, Wv, uv, bv);
    transpose_kernel<<<dim3(32, 16, BATCH), dim3(32, 8)>>>(x);
    proj_qk_kernel<<<dim3(8, 1, BATCH), 256, SMEM>>>();
    proj_v_kernel<<<dim3(4, 8, BATCH), 256, SMEM>>>();
    qk_kernel<<<dim3(8, 8, BATCH), 256, SMEM>>>();
    softmax_kernel<<<dim3(N_TOK, BATCH), 256>>>();
    av_kernel<<<dim3(4, 8, BATCH), 256, SMEM>>>(x, gamma, out);
}